// round 4
// baseline (speedup 1.0000x reference)
#include <cuda_runtime.h>
#include <stdint.h>

// KVCache_9526237462719:
//   input_pos: int32[S], k_val/v_val: f32[B,H,S,D], k_cache/v_cache: f32[B,H,BLOCK,D]
//   out = [k_cache.at[:,:,pos].set(k_val)[:,:,:S,:], same for v] concat, f32.
#define KB      4
#define KH      32
#define KS      1024
#define KD      128
#define KBLOCK  4096

#define D4      (KD / 4)                 // 32 float4 per row
#define HALF4   (4u * KH * KS * D4)      // 4,194,304 = 2^22
#define TOTAL4  (2u * HALF4)             // 8,388,608 = 2^23

#define NTHREADS 512
#define UNROLL   8
#define NBLOCKS  2048                    // 2048*512 = 2^20 threads
#define STRIDE   (1u << 20)              // NTHREADS*NBLOCKS; UNROLL*STRIDE = TOTAL4

__global__ __launch_bounds__(NTHREADS)
void kv_fused_kernel(const int*    __restrict__ input_pos,
                     const float4* __restrict__ k_val,
                     const float4* __restrict__ v_val,
                     const float4* __restrict__ k_cache,
                     const float4* __restrict__ v_cache,
                     float4*       __restrict__ out) {
    __shared__ int inv[KS];

    // Build inv[p] = s with input_pos[s] == p, else -1.  KS == 2*NTHREADS.
    #pragma unroll
    for (int t = threadIdx.x; t < KS; t += NTHREADS) inv[t] = -1;
    __syncthreads();
    #pragma unroll
    for (int s = threadIdx.x; s < KS; s += NTHREADS) {
        int p = input_pos[s];
        if ((unsigned)p < (unsigned)KS) inv[p] = s;
    }
    __syncthreads();

    // i0 in [0, 2^20); element u handles i = i0 + u*2^20.
    // Because STRIDE is a multiple of 2^15 (= S*D4), d4 and p are invariant
    // across u, is_v = (u >= 4) is compile-time, and bh = bh0 + (u&3)*32.
    unsigned i0  = blockIdx.x * NTHREADS + threadIdx.x;
    unsigned d4  = i0 & (D4 - 1);
    unsigned r0  = i0 >> 5;
    unsigned p   = r0 & (KS - 1);
    unsigned bh0 = r0 >> 10;              // < 32

    int s = inv[p];                       // ONE lookup per thread

    const float4* kbase;
    const float4* vbase;
    unsigned bstride;                     // float4s per bh step
    if (s >= 0) {
        kbase   = k_val + (unsigned)s * D4 + d4;
        vbase   = v_val + (unsigned)s * D4 + d4;
        bstride = KS * D4;                // 32768
    } else {
        kbase   = k_cache + p * D4 + d4;
        vbase   = v_cache + p * D4 + d4;
        bstride = KBLOCK * D4;            // 131072
    }

    float4 r[UNROLL];
    #pragma unroll
    for (int uu = 0; uu < 4; uu++) {
        r[uu] = __ldcs(kbase + (size_t)(bh0 + uu * 32u) * bstride);
    }
    #pragma unroll
    for (int uu = 0; uu < 4; uu++) {
        r[4 + uu] = __ldcs(vbase + (size_t)(bh0 + uu * 32u) * bstride);
    }
    #pragma unroll
    for (int u = 0; u < UNROLL; u++) {
        __stcs(out + (i0 + u * STRIDE), r[u]);
    }
}

extern "C" void kernel_launch(void* const* d_in, const int* in_sizes, int n_in,
                              void* d_out, int out_size) {
    const int*    input_pos = (const int*)d_in[0];
    const float4* k_val     = (const float4*)d_in[1];
    const float4* v_val     = (const float4*)d_in[2];
    const float4* k_cache   = (const float4*)d_in[3];
    const float4* v_cache   = (const float4*)d_in[4];
    float4*       out       = (float4*)d_out;

    kv_fused_kernel<<<NBLOCKS, NTHREADS>>>(input_pos, k_val, v_val,
                                           k_cache, v_cache, out);
}

// round 5
// speedup vs baseline: 1.0014x; 1.0014x over previous
#include <cuda_runtime.h>
#include <stdint.h>

// KVCache_9526237462719:
//   input_pos: int32[S], k_val/v_val: f32[B,H,S,D], k_cache/v_cache: f32[B,H,BLOCK,D]
//   out = [k_cache.at[:,:,pos].set(k_val)[:,:,:S,:], same for v] concat, f32.
#define KB      4
#define KH      32
#define KS      1024
#define KD      128
#define KBLOCK  4096

#define D4      (KD / 4)                 // 32 float4 per row
#define HALF4   (4u * KH * KS * D4)      // 4,194,304 = 2^22
#define TOTAL4  (2u * HALF4)             // 8,388,608 = 2^23

#define NTHREADS 512
#define UNROLL   4
#define NBLOCKS  4096                    // 4096*512 = 2^21 threads
#define STRIDE   (1u << 21)              // UNROLL*STRIDE = TOTAL4

__global__ __launch_bounds__(NTHREADS)
void kv_fused_kernel(const int*    __restrict__ input_pos,
                     const float4* __restrict__ k_val,
                     const float4* __restrict__ v_val,
                     const float4* __restrict__ k_cache,
                     const float4* __restrict__ v_cache,
                     float4*       __restrict__ out) {
    __shared__ int inv[KS];

    // Build inv[p] = s with input_pos[s] == p, else -1.  KS == 2*NTHREADS.
    #pragma unroll
    for (int t = threadIdx.x; t < KS; t += NTHREADS) inv[t] = -1;
    __syncthreads();
    #pragma unroll
    for (int s = threadIdx.x; s < KS; s += NTHREADS) {
        int p = input_pos[s];
        if ((unsigned)p < (unsigned)KS) inv[p] = s;
    }
    __syncthreads();

    // i0 in [0, 2^21); slot u handles i = i0 + u*2^21.
    //   is_v = (u >= 2)            -- compile-time
    //   d4, p invariant across u   (2^21 is a multiple of S*D4 = 2^15)
    //   bh   = bh0 + (u&1)*64      (bh0 < 64)
    unsigned i0  = blockIdx.x * NTHREADS + threadIdx.x;
    unsigned d4  = i0 & (D4 - 1);
    unsigned r0  = i0 >> 5;
    unsigned p   = r0 & (KS - 1);
    unsigned bh0 = r0 >> 10;              // < 64

    int s = inv[p];                       // ONE smem lookup per thread

    const float4* kbase;
    const float4* vbase;
    unsigned bstride;                     // float4s per bh step
    if (s >= 0) {
        kbase   = k_val + (unsigned)s * D4 + d4;
        vbase   = v_val + (unsigned)s * D4 + d4;
        bstride = KS * D4;                // 32768
    } else {
        kbase   = k_cache + p * D4 + d4;
        vbase   = v_cache + p * D4 + d4;
        bstride = KBLOCK * D4;            // 131072
    }

    float4 r[UNROLL];
    r[0] = __ldcs(kbase + (size_t)bh0 * bstride);
    r[1] = __ldcs(kbase + (size_t)(bh0 + 64u) * bstride);
    r[2] = __ldcs(vbase + (size_t)bh0 * bstride);
    r[3] = __ldcs(vbase + (size_t)(bh0 + 64u) * bstride);

    #pragma unroll
    for (int u = 0; u < UNROLL; u++) {
        __stcs(out + (i0 + u * STRIDE), r[u]);
    }
}

extern "C" void kernel_launch(void* const* d_in, const int* in_sizes, int n_in,
                              void* d_out, int out_size) {
    const int*    input_pos = (const int*)d_in[0];
    const float4* k_val     = (const float4*)d_in[1];
    const float4* v_val     = (const float4*)d_in[2];
    const float4* k_cache   = (const float4*)d_in[3];
    const float4* v_cache   = (const float4*)d_in[4];
    float4*       out       = (float4*)d_out;

    kv_fused_kernel<<<NBLOCKS, NTHREADS>>>(input_pos, k_val, v_val,
                                           k_cache, v_cache, out);
}